// round 7
// baseline (speedup 1.0000x reference)
#include <cuda_runtime.h>
#include <cuda_bf16.h>
#include <cstdint>

#define BATCH 16
#define PD    31
#define COUT  16

#define A_PLANE 1088                         // 68 x-slots * 16B
#define A_BYTES (32 * A_PLANE)               // 34816 : [z4][y8] planes
#define B_BYTES (9 * 2 * 16 * 16 * 2)        // 9216
#define AOFF    0
#define BOFF    A_BYTES                      // 34816
#define POOLOFF (BOFF + B_BYTES)             // 44032 : 2 x [2 oy][32 px][16 co]
#define RED2OFF (POOLOFF + 8192)             // 52224
#define SMEM_BYTES (RED2OFF + 1024)          // 53248

__device__ float g_part[BATCH * PD * COUT];

__device__ __forceinline__ uint32_t smem_u32(const void* p) {
    uint32_t a;
    asm("{ .reg .u64 t; cvta.to.shared.u64 t, %1; cvt.u32.u64 %0, t; }"
        : "=r"(a) : "l"(p));
    return a;
}

__device__ __forceinline__ uint32_t lds32(uint32_t addr) {
    uint32_t v;
    asm volatile("ld.shared.b32 %0, [%1];" : "=r"(v) : "r"(addr));
    return v;
}

__device__ __forceinline__ void ldsm4(uint32_t (&a)[4], uint32_t addr) {
    asm volatile("ldmatrix.sync.aligned.m8n8.x4.shared.b16 {%0,%1,%2,%3}, [%4];"
                 : "=r"(a[0]), "=r"(a[1]), "=r"(a[2]), "=r"(a[3]) : "r"(addr));
}

__device__ __forceinline__ void mma16816(float (&d)[4], const uint32_t (&a)[4],
                                         uint32_t b0, uint32_t b1) {
    asm volatile(
        "mma.sync.aligned.m16n8k16.row.col.f32.bf16.bf16.f32 "
        "{%0,%1,%2,%3}, {%4,%5,%6,%7}, {%8,%9}, {%0,%1,%2,%3};"
        : "+f"(d[0]), "+f"(d[1]), "+f"(d[2]), "+f"(d[3])
        : "r"(a[0]), "r"(a[1]), "r"(a[2]), "r"(a[3]), "r"(b0), "r"(b1));
}

__device__ __forceinline__ uint32_t bfpack(float fhi, float flo) {
    uint32_t r;
    asm("cvt.rn.bf16x2.f32 %0, %1, %2;" : "=r"(r) : "f"(fhi), "f"(flo));
    return r;
}

__global__ __launch_bounds__(256, 1)
void conv_mma_kernel(const float* __restrict__ x, const float* __restrict__ cw,
                     int pz0, int npz) {
    extern __shared__ __align__(1024) char smem[];
    const uint32_t sbase = smem_u32(smem);
    const int tid  = threadIdx.x;
    const int wid  = tid >> 5;
    const int lane = tid & 31;
    const int b    = blockIdx.x / npz;
    const int pz   = pz0 + (blockIdx.x - b * npz);
    const float* xb = x + (size_t)b * 2097152;

    // ---- B tiles: [win9][kstep2][n16][k16] bf16 ----
    for (int i = tid; i < 4608; i += 256) {
        int k = i & 15, n = (i >> 4) & 15;
        int ks = (i >> 8) & 1, win = i >> 9;
        int dz = win / 3, dy = win % 3;
        int dxl = k >> 3, cin = k & 7, dx = ks * 2 + dxl;
        float w = (dx < 3) ? cw[(((n * 8 + cin) * 3 + dz) * 3 + dy) * 3 + dx] : 0.0f;
        *(__nv_bfloat16*)(smem + BOFF + i * 2) = __float2bfloat16(w);
    }
    // ---- zero x-pad slots (x=64..67) in all 32 planes ----
    for (int i = tid; i < 32 * 4 * 8; i += 256) {
        int p = i >> 5, xs = (i >> 3) & 3, c = i & 7;
        *(__nv_bfloat16*)(smem + AOFF + p * A_PLANE + (64 + xs) * 16 + c * 2) =
            __float2bfloat16(0.0f);
    }

    const int cp = tid & 3;
    const int xg = tid >> 2;
    auto ldrows = [&](int y0, uint32_t (&pk)[8]) {
#pragma unroll
        for (int j = 0; j < 8; ++j) {
            int zi = j >> 1, yy = j & 1;
            size_t base = ((size_t)((2 * cp) * 64 + (2 * pz + zi)) * 64 + (y0 + yy)) * 64 + xg;
            pk[j] = bfpack(xb[base + 262144], xb[base]);
        }
    };
    auto strows = [&](int y0, const uint32_t (&pk)[8]) {
#pragma unroll
        for (int j = 0; j < 8; ++j) {
            int zi = j >> 1, yy = j & 1;
            int yb = (y0 + yy) & 7;
            *(uint32_t*)(smem + AOFF + (zi * 8 + yb) * A_PLANE + xg * 16 + cp * 4) = pk[j];
        }
    };

    {   // initial rows 0..3 -> slots 0..3
        uint32_t pk[8];
        ldrows(0, pk); strows(0, pk);
        ldrows(2, pk); strows(2, pk);
    }
    __syncthreads();

    const int oy   = wid >> 2;
    const int x0   = (wid & 3) * 16;
    const int r8   = lane & 7;
    const int matm = (lane >> 3) & 1;
    const int kh   = lane >> 4;
    const uint32_t laneA = sbase + AOFF + (x0 + matm * 8 + r8) * 16 + kh * 16;
    const uint32_t laneB = sbase + BOFF + (lane >> 2) * 32 + (lane & 3) * 4;

    // ---- hoist all B fragments into registers ----
    uint32_t Breg[9][2][2][2];
#pragma unroll
    for (int win = 0; win < 9; ++win)
#pragma unroll
        for (int ks = 0; ks < 2; ++ks)
#pragma unroll
            for (int nt = 0; nt < 2; ++nt) {
                uint32_t a_ = laneB + win * 1024 + ks * 512 + nt * 256;
                Breg[win][ks][nt][0] = lds32(a_);
                Breg[win][ks][nt][1] = lds32(a_ + 16);
            }

    float racc0 = 0.0f, racc1 = 0.0f;
    const int rpx = tid >> 4, rco = tid & 15;

    uint32_t kept[4][2][4], atmp[4][2][4];
    float acc[2][2][4];

    auto load_dy = [&](uint32_t (&a)[4][2][4], int t, int dy) {
        const int yb = (2 * t + oy + dy) & 7;
#pragma unroll
        for (int zb = 0; zb < 4; ++zb) {
            const uint32_t pb = laneA + (zb * 8 + yb) * A_PLANE;
            ldsm4(a[zb][0], pb);
            ldsm4(a[zb][1], pb + 32);
        }
    };
    auto mma_dy = [&](const uint32_t (&a)[4][2][4], int dy) {
#pragma unroll
        for (int dz = 0; dz < 3; ++dz)
#pragma unroll
            for (int ks = 0; ks < 2; ++ks)
#pragma unroll
                for (int nt = 0; nt < 2; ++nt)
#pragma unroll
                    for (int oz = 0; oz < 2; ++oz)
                        mma16816(acc[oz][nt], a[oz + dz][ks],
                                 Breg[dz * 3 + dy][ks][nt][0],
                                 Breg[dz * 3 + dy][ks][nt][1]);
    };

    load_dy(kept, 0, 0);

    for (int t = 0; t < PD; ++t) {
        uint32_t pk[8];
        const bool pre = (t < PD - 1);
        if (pre) ldrows(2 * t + 4, pk);

#pragma unroll
        for (int oz = 0; oz < 2; ++oz)
#pragma unroll
            for (int nt = 0; nt < 2; ++nt)
#pragma unroll
                for (int j = 0; j < 4; ++j) acc[oz][nt][j] = 0.0f;

        load_dy(atmp, t, 1);
        mma_dy(kept, 0);          // dy=0 fragments carried from last iter
        mma_dy(atmp, 1);
        load_dy(kept, t, 2);      // becomes dy=0 of next iter
        mma_dy(kept, 2);

        // ---- epilogue: max over oz, x-pair max via shfl ----
        float* pool = (float*)(smem + POOLOFF + (t & 1) * 4096);
        float m[2][4];
#pragma unroll
        for (int nt = 0; nt < 2; ++nt)
#pragma unroll
            for (int j = 0; j < 4; ++j) {
                float v = fmaxf(acc[0][nt][j], acc[1][nt][j]);
                m[nt][j] = fmaxf(v, __shfl_xor_sync(0xffffffffu, v, 4));
            }
        if (((lane >> 2) & 1) == 0) {
            const int pxl = (lane >> 2) >> 1;
            const int px_ = (wid & 3) * 8 + pxl;
            const int c0  = 2 * (lane & 3);
            float* p0 = pool + (oy * 32 + px_) * 16;
            float* p1 = pool + (oy * 32 + px_ + 4) * 16;
            p0[c0]     = m[0][0];  p0[c0 + 1]     = m[0][1];
            p1[c0]     = m[0][2];  p1[c0 + 1]     = m[0][3];
            p0[8 + c0] = m[1][0];  p0[8 + c0 + 1] = m[1][1];
            p1[8 + c0] = m[1][2];  p1[8 + c0 + 1] = m[1][3];
        }
        if (pre) strows(2 * t + 4, pk);   // disjoint slots from rows in flight
        __syncthreads();                  // single sync per iteration

        racc0 += fmaxf(pool[rpx * 16 + rco], pool[(32 + rpx) * 16 + rco]);
        const int px2 = rpx + 16;
        if (px2 < 31)
            racc1 += fmaxf(pool[px2 * 16 + rco], pool[(32 + px2) * 16 + rco]);
    }

    float* red2 = (float*)(smem + RED2OFF);
    red2[rco * 16 + rpx] = racc0 + racc1;
    __syncthreads();
    if (tid < COUT) {
        float s = 0.0f;
#pragma unroll
        for (int k = 0; k < 16; ++k) s += red2[tid * 16 + k];
        g_part[(b * PD + pz) * COUT + tid] = s;
    }
}

__global__ void final_kernel(const float* __restrict__ cb,
                             const float* __restrict__ bias,
                             float* __restrict__ out) {
    __shared__ float sacc[256];
    const int t = threadIdx.x;
    const int b = t >> 4, co = t & 15;
    float S = 0.0f;
    for (int pz = 0; pz < PD; ++pz)
        S += g_part[(b * PD + pz) * COUT + co];
    sacc[t] = S * (0.5f / 29791.0f) + 0.5f * cb[co] + bias[co];
    __syncthreads();
    if (co == 0) {
        float s = 0.0f;
#pragma unroll
        for (int k = 0; k < COUT; ++k) s += sacc[b * COUT + k];
        out[b] = s;
    }
}

extern "C" void kernel_launch(void* const* d_in, const int* in_sizes, int n_in,
                              void* d_out, int out_size) {
    (void)in_sizes; (void)n_in; (void)out_size;
    const float* x    = (const float*)d_in[0];
    const float* cw   = (const float*)d_in[1];
    const float* cb   = (const float*)d_in[2];
    const float* bias = (const float*)d_in[3];
    float* out = (float*)d_out;

    cudaFuncSetAttribute(conv_mma_kernel,
                         cudaFuncAttributeMaxDynamicSharedMemorySize, SMEM_BYTES);

    conv_mma_kernel<<<BATCH * 16, 256, SMEM_BYTES>>>(x, cw, 0, 16);
    conv_mma_kernel<<<BATCH * 15, 256, SMEM_BYTES>>>(x, cw, 16, 15);
    final_kernel<<<1, 256>>>(cb, bias, out);
}